// round 2
// baseline (speedup 1.0000x reference)
#include <cuda_runtime.h>
#include <cuda_bf16.h>
#include <cstdint>

// ---------------------------------------------------------------------------
// Scratch (static __device__ arrays — allocation-free per harness rules)
// Q: [B*3136, 512] bf16 ; K,V: [B*784, 512] bf16  (B=32)
// ---------------------------------------------------------------------------
static __device__ __nv_bfloat16 g_Q[(size_t)100352 * 512];
static __device__ __nv_bfloat16 g_K[(size_t)25088 * 512];
static __device__ __nv_bfloat16 g_V[(size_t)25088 * 512];

// ---------------------------------------------------------------------------
// mma.sync m16n8k16 bf16 (row.col), fp32 accum
// ---------------------------------------------------------------------------
__device__ __forceinline__ void mma16816(float* c, const uint32_t* a, const uint32_t* b) {
    asm volatile(
        "mma.sync.aligned.m16n8k16.row.col.f32.bf16.bf16.f32 "
        "{%0,%1,%2,%3}, {%4,%5,%6,%7}, {%8,%9}, {%0,%1,%2,%3};\n"
        : "+f"(c[0]), "+f"(c[1]), "+f"(c[2]), "+f"(c[3])
        : "r"(a[0]), "r"(a[1]), "r"(a[2]), "r"(a[3]), "r"(b[0]), "r"(b[1]));
}

// packed fp32x2 FMA (Blackwell): c += a * b elementwise
__device__ __forceinline__ void fma2(float2& c, float2 a, float2 b) {
    unsigned long long uc = *reinterpret_cast<unsigned long long*>(&c);
    unsigned long long ua = *reinterpret_cast<unsigned long long*>(&a);
    unsigned long long ub = *reinterpret_cast<unsigned long long*>(&b);
    asm("fma.rn.f32x2 %0, %1, %2, %0;" : "+l"(uc) : "l"(ua), "l"(ub));
    c = *reinterpret_cast<float2*>(&uc);
}

// ---------------------------------------------------------------------------
// Projection GEMM:  Out[m,n] = sum_k A[m,k] * W[n,k] + bias[n]   (K = N = 512)
// A fp32 [M,512] row-major, W fp32 [512,512] row-major (n rows), Out bf16.
// Tile 128x128, BK=32, 8 warps (2x4), warp tile 64x32, double-buffered smem.
// Smem rows padded to 40 bf16 -> conflict-free 32b fragment loads.
// ---------------------------------------------------------------------------
__global__ void __launch_bounds__(256) proj_gemm_kernel(
    const float* __restrict__ A, const float* __restrict__ W,
    const float* __restrict__ bias, int which)
{
    __shared__ __nv_bfloat16 As[2][128 * 40];
    __shared__ __nv_bfloat16 Bs[2][128 * 40];

    __nv_bfloat16* O = (which == 0) ? g_Q : (which == 1) ? g_K : g_V;

    const int m0 = blockIdx.y * 128;
    const int n0 = blockIdx.x * 128;
    const int tid = threadIdx.x;
    const int w = tid >> 5, lane = tid & 31;
    const int wm = w >> 2, wn = w & 3;       // 2 x 4 warp grid
    const int g = lane >> 2, tg = lane & 3;  // mma fragment coords

    float acc[4][4][4];
#pragma unroll
    for (int mt = 0; mt < 4; mt++)
#pragma unroll
        for (int nt = 0; nt < 4; nt++)
#pragma unroll
            for (int q = 0; q < 4; q++) acc[mt][nt][q] = 0.f;

    const int lr = tid >> 3;        // 0..31 (row within 32-row slab)
    const int lc = (tid & 7) * 4;   // 0..28 (k offset, float4)

    auto load_tiles = [&](int buf, int k0) {
#pragma unroll
        for (int it = 0; it < 4; it++) {
            const int row = lr + it * 32;
            const float4 va = *(const float4*)&A[(size_t)(m0 + row) * 512 + k0 + lc];
            const float4 vb = *(const float4*)&W[(size_t)(n0 + row) * 512 + k0 + lc];
            __nv_bfloat162* da = (__nv_bfloat162*)&As[buf][row * 40 + lc];
            da[0] = __floats2bfloat162_rn(va.x, va.y);
            da[1] = __floats2bfloat162_rn(va.z, va.w);
            __nv_bfloat162* db = (__nv_bfloat162*)&Bs[buf][row * 40 + lc];
            db[0] = __floats2bfloat162_rn(vb.x, vb.y);
            db[1] = __floats2bfloat162_rn(vb.z, vb.w);
        }
    };

    load_tiles(0, 0);
    __syncthreads();
    int buf = 0;
#pragma unroll 1
    for (int kb = 0; kb < 16; kb++) {
        if (kb < 15) load_tiles(buf ^ 1, (kb + 1) * 32);
#pragma unroll
        for (int ks = 0; ks < 2; ks++) {
            const int k16 = ks * 16;
            uint32_t ar[4][4], br[4][2];
#pragma unroll
            for (int mt = 0; mt < 4; mt++) {
                const int mr = wm * 64 + mt * 16;
                ar[mt][0] = *(const uint32_t*)&As[buf][(mr + g) * 40 + k16 + tg * 2];
                ar[mt][1] = *(const uint32_t*)&As[buf][(mr + g + 8) * 40 + k16 + tg * 2];
                ar[mt][2] = *(const uint32_t*)&As[buf][(mr + g) * 40 + k16 + tg * 2 + 8];
                ar[mt][3] = *(const uint32_t*)&As[buf][(mr + g + 8) * 40 + k16 + tg * 2 + 8];
            }
#pragma unroll
            for (int nt = 0; nt < 4; nt++) {
                const int nc = wn * 32 + nt * 8;
                br[nt][0] = *(const uint32_t*)&Bs[buf][(nc + g) * 40 + k16 + tg * 2];
                br[nt][1] = *(const uint32_t*)&Bs[buf][(nc + g) * 40 + k16 + tg * 2 + 8];
            }
#pragma unroll
            for (int mt = 0; mt < 4; mt++)
#pragma unroll
                for (int nt = 0; nt < 4; nt++)
                    mma16816(acc[mt][nt], ar[mt], br[nt]);
        }
        __syncthreads();
        buf ^= 1;
    }

    // epilogue: +bias, convert to bf16, store
#pragma unroll
    for (int mt = 0; mt < 4; mt++) {
#pragma unroll
        for (int nt = 0; nt < 4; nt++) {
            const int mr = m0 + wm * 64 + mt * 16 + g;
            const int nc = n0 + wn * 32 + nt * 8 + tg * 2;
            const float b0 = bias[nc], b1 = bias[nc + 1];
            const __nv_bfloat162 v0 =
                __floats2bfloat162_rn(acc[mt][nt][0] + b0, acc[mt][nt][1] + b1);
            const __nv_bfloat162 v1 =
                __floats2bfloat162_rn(acc[mt][nt][2] + b0, acc[mt][nt][3] + b1);
            *(__nv_bfloat162*)&O[(size_t)mr * 512 + nc] = v0;
            *(__nv_bfloat162*)&O[(size_t)(mr + 8) * 512 + nc] = v1;
        }
    }
}

// ---------------------------------------------------------------------------
// Fused patch attention. One CTA per (p, b). 256 threads = 8 warps.
// Each warp owns 8 q-rows (2 groups of 4, register-blocked).
//   logits  S = q @ k^T * C^-0.5   (fp32 accum from bf16)
//   attn    = softmax(S) * gate(row)   (gate folded into weights)
//   out     = attn @ v + lo_p  -> fp32, written at unpatched token positions
// ---------------------------------------------------------------------------
__global__ void __launch_bounds__(256) attn_kernel(
    const float* __restrict__ lo, const float* __restrict__ Ws,
    const float* __restrict__ bs, float* __restrict__ out)
{
    __shared__ __nv_bfloat16 Ks[16 * 512];
    __shared__ __nv_bfloat16 Vs[16 * 512];
    __shared__ __align__(16) float Wss[512];
    __shared__ float gateS[64];

    const int p = blockIdx.x, b = blockIdx.y;
    const int py = p / 7, px = p % 7;
    const int tid = threadIdx.x;
    const int w = tid >> 5, lane = tid & 31;

    for (int i = tid; i < 512; i += 256) Wss[i] = Ws[i];

    // gather K,V patch (16 hi-tokens x 512) into smem, 8B vectors
    const size_t kvbase = (size_t)b * 784;
    for (int idx = tid; idx < 2048; idx += 256) {
        const int j = idx >> 7;            // kv token within patch
        const int c4 = (idx & 127) * 4;    // channel (x4)
        const int jy = j >> 2, jx = j & 3;
        const size_t src = (kvbase + (size_t)((py * 4 + jy) * 28 + (px * 4 + jx))) * 512 + c4;
        *(uint2*)&Ks[j * 512 + c4] = *(const uint2*)&g_K[src];
        *(uint2*)&Vs[j * 512 + c4] = *(const uint2*)&g_V[src];
    }
    __syncthreads();

    // per-row gate = GELU(lo_row . Ws + bs)  (warp w does rows w*8..w*8+7)
    const float bsv = bs[0];
    for (int rr = 0; rr < 8; rr++) {
        const int n = w * 8 + rr;
        const int iy = n >> 3, ix = n & 7;
        const size_t lrow = ((size_t)b * 3136 + (size_t)((py * 8 + iy) * 56 + (px * 8 + ix))) * 512;
        float s = 0.f;
#pragma unroll
        for (int i = 0; i < 4; i++) {
            const float4 x = *(const float4*)&lo[lrow + (lane + 32 * i) * 4];
            const float4 wv = *(const float4*)&Wss[(lane + 32 * i) * 4];
            s += x.x * wv.x + x.y * wv.y + x.z * wv.z + x.w * wv.w;
        }
#pragma unroll
        for (int o = 16; o > 0; o >>= 1) s += __shfl_xor_sync(0xffffffffu, s, o);
        if (lane == 0) {
            const float x = s + bsv;
            gateS[n] = 0.5f * x * (1.f + erff(x * 0.70710678118f));
        }
    }
    __syncthreads();

    const float scale = 0.044194173824159216f;  // 512^-0.5

#pragma unroll 1
    for (int grp = 0; grp < 2; grp++) {
        const int r0 = w * 8 + grp * 4;
        size_t lrow[4];
#pragma unroll
        for (int r = 0; r < 4; r++) {
            const int n = r0 + r;
            const int iy = n >> 3, ix = n & 7;
            lrow[r] = ((size_t)b * 3136 + (size_t)((py * 8 + iy) * 56 + (px * 8 + ix))) * 512;
        }

        // ---- logits: lane accumulates partial dot over its channel slice ----
        float sacc[4][16];
#pragma unroll
        for (int r = 0; r < 4; r++)
#pragma unroll
            for (int j = 0; j < 16; j++) sacc[r][j] = 0.f;

#pragma unroll
        for (int i = 0; i < 8; i++) {
            const int c2 = lane + 32 * i;  // bf16x2 index, channels 2c2, 2c2+1
            float2 q[4];
#pragma unroll
            for (int r = 0; r < 4; r++)
                q[r] = __bfloat1622float2(*(const __nv_bfloat162*)&g_Q[lrow[r] + 2 * c2]);
#pragma unroll
            for (int j = 0; j < 16; j++) {
                const float2 kk =
                    __bfloat1622float2(*(const __nv_bfloat162*)&Ks[j * 512 + 2 * c2]);
#pragma unroll
                for (int r = 0; r < 4; r++)
                    sacc[r][j] += q[r].x * kk.x + q[r].y * kk.y;
            }
        }
        // butterfly reduce -> every lane holds full sums
#pragma unroll
        for (int o = 16; o > 0; o >>= 1)
#pragma unroll
            for (int r = 0; r < 4; r++)
#pragma unroll
                for (int j = 0; j < 16; j++)
                    sacc[r][j] += __shfl_xor_sync(0xffffffffu, sacc[r][j], o);

        // ---- softmax (redundant per lane) + fold gate ----
#pragma unroll
        for (int r = 0; r < 4; r++) {
            float m = sacc[r][0];
#pragma unroll
            for (int j = 1; j < 16; j++) m = fmaxf(m, sacc[r][j]);
            float ssum = 0.f;
#pragma unroll
            for (int j = 0; j < 16; j++) {
                const float e = __expf((sacc[r][j] - m) * scale);
                sacc[r][j] = e;
                ssum += e;
            }
            const float gm = gateS[r0 + r] / ssum;
#pragma unroll
            for (int j = 0; j < 16; j++) sacc[r][j] *= gm;
        }

        // ---- out = attn @ V + lo_p ----
#pragma unroll
        for (int i = 0; i < 8; i++) {
            const int c2 = lane + 32 * i;
            float2 acc[4];
#pragma unroll
            for (int r = 0; r < 4; r++) acc[r] = make_float2(0.f, 0.f);
#pragma unroll
            for (int j = 0; j < 16; j++) {
                const float2 vv =
                    __bfloat1622float2(*(const __nv_bfloat162*)&Vs[j * 512 + 2 * c2]);
#pragma unroll
                for (int r = 0; r < 4; r++)
                    fma2(acc[r], make_float2(sacc[r][j], sacc[r][j]), vv);
            }
#pragma unroll
            for (int r = 0; r < 4; r++) {
                const float2 res = *(const float2*)&lo[lrow[r] + 2 * c2];
                float2 o;
                o.x = acc[r].x + res.x;
                o.y = acc[r].y + res.y;
                *(float2*)&out[lrow[r] + 2 * c2] = o;
            }
        }
    }
}

// ---------------------------------------------------------------------------
// launch
// ---------------------------------------------------------------------------
extern "C" void kernel_launch(void* const* d_in, const int* in_sizes, int n_in,
                              void* d_out, int out_size) {
    const float* lo = (const float*)d_in[0];
    const float* hi = (const float*)d_in[1];
    const float* Wq = (const float*)d_in[2];
    const float* bq = (const float*)d_in[3];
    const float* Wk = (const float*)d_in[4];
    const float* bk = (const float*)d_in[5];
    const float* Wv = (const float*)d_in[6];
    const float* bv = (const float*)d_in[7];
    const float* Ws = (const float*)d_in[8];
    const float* bs = (const float*)d_in[9];
    float* out = (float*)d_out;

    const int B = in_sizes[0] / (3136 * 512);   // 32
    const int mQ = (B * 3136) / 128;            // 784
    const int mKV = (B * 784) / 128;            // 196

    proj_gemm_kernel<<<dim3(4, mQ), 256>>>(lo, Wq, bq, 0);
    proj_gemm_kernel<<<dim3(4, mKV), 256>>>(hi, Wk, bk, 1);
    proj_gemm_kernel<<<dim3(4, mKV), 256>>>(hi, Wv, bv, 2);
    attn_kernel<<<dim3(49, B), 256>>>(lo, Ws, bs, out);
}

// round 4
// speedup vs baseline: 1.3758x; 1.3758x over previous
#include <cuda_runtime.h>
#include <cuda_bf16.h>
#include <cstdint>

// ---------------------------------------------------------------------------
// Scratch
// ---------------------------------------------------------------------------
static __device__ __nv_bfloat16 g_Q[(size_t)100352 * 512];
static __device__ __nv_bfloat16 g_K[(size_t)25088 * 512];
static __device__ __nv_bfloat16 g_V[(size_t)25088 * 512];

// ---------------------------------------------------------------------------
// mma.sync m16n8k16 bf16 (row.col), fp32 accum
// ---------------------------------------------------------------------------
__device__ __forceinline__ void mma16816(float* c, const uint32_t* a, const uint32_t* b) {
    asm volatile(
        "mma.sync.aligned.m16n8k16.row.col.f32.bf16.bf16.f32 "
        "{%0,%1,%2,%3}, {%4,%5,%6,%7}, {%8,%9}, {%0,%1,%2,%3};\n"
        : "+f"(c[0]), "+f"(c[1]), "+f"(c[2]), "+f"(c[3])
        : "r"(a[0]), "r"(a[1]), "r"(a[2]), "r"(a[3]), "r"(b[0]), "r"(b[1]));
}

__device__ __forceinline__ void fma2(float2& c, float2 a, float2 b) {
    unsigned long long uc = *reinterpret_cast<unsigned long long*>(&c);
    unsigned long long ua = *reinterpret_cast<unsigned long long*>(&a);
    unsigned long long ub = *reinterpret_cast<unsigned long long*>(&b);
    asm("fma.rn.f32x2 %0, %1, %2, %0;" : "+l"(uc) : "l"(ua), "l"(ub));
    c = *reinterpret_cast<float2*>(&uc);
}

// ---------------------------------------------------------------------------
// Projection GEMM, software-pipelined.
//   which == 0 : Out = g_Q,  A = lo, weights Wa (grid.x = 4)
//   which == 1 : merged K|V, A = hi, nblk<4 -> (Wa=Wk,g_K), else (Wb=Wv,g_V)
// Tile 128x128, BK=32, 8 warps (2x4), warp tile 64x32, double-buffered bf16
// smem (rows padded to 40). Staged loads split in 2 rounds around the 2 mma
// half-steps so LDG latency hides behind HMMA.
// ---------------------------------------------------------------------------
__global__ void __launch_bounds__(256, 2) proj_gemm_kernel(
    const float* __restrict__ A,
    const float* __restrict__ Wa, const float* __restrict__ ba,
    const float* __restrict__ Wb, const float* __restrict__ bb,
    int which)
{
    __shared__ __nv_bfloat16 As[2][128 * 40];
    __shared__ __nv_bfloat16 Bs[2][128 * 40];

    const int nblk = blockIdx.x;
    const float* W = Wa;
    const float* bias = ba;
    __nv_bfloat16* O = g_Q;
    int n0 = nblk * 128;
    if (which == 1) {
        if (nblk < 4) { W = Wa; bias = ba; O = g_K; n0 = nblk * 128; }
        else          { W = Wb; bias = bb; O = g_V; n0 = (nblk - 4) * 128; }
    }

    const int m0 = blockIdx.y * 128;
    const int tid = threadIdx.x;
    const int w = tid >> 5, lane = tid & 31;
    const int wm = w >> 2, wn = w & 3;
    const int g = lane >> 2, tg = lane & 3;

    float acc[4][4][4];
#pragma unroll
    for (int mt = 0; mt < 4; mt++)
#pragma unroll
        for (int nt = 0; nt < 4; nt++)
#pragma unroll
            for (int q = 0; q < 4; q++) acc[mt][nt][q] = 0.f;

    const int lr = tid >> 3;
    const int lc = (tid & 7) * 4;

    float4 sa[2], sb[2];

    auto ldg_round = [&](int rnd, int k0) {
#pragma unroll
        for (int t = 0; t < 2; t++) {
            const int row = lr + (rnd * 2 + t) * 32;
            sa[t] = *(const float4*)&A[(size_t)(m0 + row) * 512 + k0 + lc];
            sb[t] = *(const float4*)&W[(size_t)(n0 + row) * 512 + k0 + lc];
        }
    };
    auto sts_round = [&](int rnd, int buf) {
#pragma unroll
        for (int t = 0; t < 2; t++) {
            const int row = lr + (rnd * 2 + t) * 32;
            __nv_bfloat162* da = (__nv_bfloat162*)&As[buf][row * 40 + lc];
            da[0] = __floats2bfloat162_rn(sa[t].x, sa[t].y);
            da[1] = __floats2bfloat162_rn(sa[t].z, sa[t].w);
            __nv_bfloat162* db = (__nv_bfloat162*)&Bs[buf][row * 40 + lc];
            db[0] = __floats2bfloat162_rn(sb[t].x, sb[t].y);
            db[1] = __floats2bfloat162_rn(sb[t].z, sb[t].w);
        }
    };
    auto mma_half = [&](int buf, int k16) {
        uint32_t ar[4][4], br[4][2];
#pragma unroll
        for (int mt = 0; mt < 4; mt++) {
            const int mr = wm * 64 + mt * 16;
            ar[mt][0] = *(const uint32_t*)&As[buf][(mr + g) * 40 + k16 + tg * 2];
            ar[mt][1] = *(const uint32_t*)&As[buf][(mr + g + 8) * 40 + k16 + tg * 2];
            ar[mt][2] = *(const uint32_t*)&As[buf][(mr + g) * 40 + k16 + tg * 2 + 8];
            ar[mt][3] = *(const uint32_t*)&As[buf][(mr + g + 8) * 40 + k16 + tg * 2 + 8];
        }
#pragma unroll
        for (int nt = 0; nt < 4; nt++) {
            const int nc = wn * 32 + nt * 8;
            br[nt][0] = *(const uint32_t*)&Bs[buf][(nc + g) * 40 + k16 + tg * 2];
            br[nt][1] = *(const uint32_t*)&Bs[buf][(nc + g) * 40 + k16 + tg * 2 + 8];
        }
#pragma unroll
        for (int mt = 0; mt < 4; mt++)
#pragma unroll
            for (int nt = 0; nt < 4; nt++)
                mma16816(acc[mt][nt], ar[mt], br[nt]);
    };

    // prologue: fill buffer 0
    ldg_round(0, 0); sts_round(0, 0);
    ldg_round(1, 0); sts_round(1, 0);
    __syncthreads();

    int buf = 0;
#pragma unroll 1
    for (int kb = 0; kb < 16; kb++) {
        const int k0n = (kb + 1) * 32;
        if (kb < 15) ldg_round(0, k0n);
        mma_half(buf, 0);
        if (kb < 15) { sts_round(0, buf ^ 1); ldg_round(1, k0n); }
        mma_half(buf, 16);
        if (kb < 15) sts_round(1, buf ^ 1);
        __syncthreads();
        buf ^= 1;
    }

#pragma unroll
    for (int mt = 0; mt < 4; mt++) {
#pragma unroll
        for (int nt = 0; nt < 4; nt++) {
            const int mr = m0 + wm * 64 + mt * 16 + g;
            const int nc = n0 + wn * 32 + nt * 8 + tg * 2;
            const float b0 = bias[nc], b1 = bias[nc + 1];
            const __nv_bfloat162 v0 =
                __floats2bfloat162_rn(acc[mt][nt][0] + b0, acc[mt][nt][1] + b1);
            const __nv_bfloat162 v1 =
                __floats2bfloat162_rn(acc[mt][nt][2] + b0, acc[mt][nt][3] + b1);
            *(__nv_bfloat162*)&O[(size_t)mr * 512 + nc] = v0;
            *(__nv_bfloat162*)&O[(size_t)(mr + 8) * 512 + nc] = v1;
        }
    }
}

// ---------------------------------------------------------------------------
// Fused patch attention, tensor-core logits.
// CTA = (p, b), 256 threads / 8 warps.
//   phase 0: stage K,V patch (16x512, rows padded to 520 bf16) + gate weights
//   phase 1: gate[n] = GELU(lo_row . Ws + bs)          (warp w -> rows 8w..8w+7)
//   phase 2: warps 0..3: S = Q*K^T via m16n8k16 (warp w -> rows 16w..16w+15),
//            softmax over 16 cols on fragments (shfl_xor 1,2),
//            Wgt[row][col] = softmax * gate / sum  -> smem
//   phase 3: all warps: out = Wgt @ V + lo  (fp32, packed fma2)
// ---------------------------------------------------------------------------
__global__ void __launch_bounds__(256) attn_kernel(
    const float* __restrict__ lo, const float* __restrict__ Ws,
    const float* __restrict__ bs, float* __restrict__ out)
{
    __shared__ __nv_bfloat16 Ks[16 * 520];
    __shared__ __nv_bfloat16 Vs[16 * 520];
    __shared__ __align__(16) float Wss[512];
    __shared__ float gateS[64];
    __shared__ float Wgt[64 * 16];

    const int p = blockIdx.x, b = blockIdx.y;
    const int py = p / 7, px = p % 7;
    const int tid = threadIdx.x;
    const int w = tid >> 5, lane = tid & 31;
    const int g = lane >> 2, tg = lane & 3;

    for (int i = tid; i < 512; i += 256) Wss[i] = Ws[i];

    // stage K,V (16 hi tokens x 512ch) into padded smem
    const size_t kvbase = (size_t)b * 784;
    for (int idx = tid; idx < 2048; idx += 256) {
        const int j = idx >> 7;
        const int c4 = (idx & 127) * 4;
        const int jy = j >> 2, jx = j & 3;
        const size_t src = (kvbase + (size_t)((py * 4 + jy) * 28 + (px * 4 + jx))) * 512 + c4;
        *(uint2*)&Ks[j * 520 + c4] = *(const uint2*)&g_K[src];
        *(uint2*)&Vs[j * 520 + c4] = *(const uint2*)&g_V[src];
    }
    __syncthreads();

    // row -> lo token row offset (in elements)
    auto lo_row = [&](int n) -> size_t {
        const int iy = n >> 3, ix = n & 7;
        return ((size_t)b * 3136 + (size_t)((py * 8 + iy) * 56 + (px * 8 + ix))) * 512;
    };

    // ---- gate ----
    const float bsv = bs[0];
    for (int rr = 0; rr < 8; rr++) {
        const int n = w * 8 + rr;
        const size_t lrow = lo_row(n);
        float s = 0.f;
#pragma unroll
        for (int i = 0; i < 4; i++) {
            const float4 x = *(const float4*)&lo[lrow + (lane + 32 * i) * 4];
            const float4 wv = *(const float4*)&Wss[(lane + 32 * i) * 4];
            s += x.x * wv.x + x.y * wv.y + x.z * wv.z + x.w * wv.w;
        }
#pragma unroll
        for (int o = 16; o > 0; o >>= 1) s += __shfl_xor_sync(0xffffffffu, s, o);
        if (lane == 0) {
            const float x = s + bsv;
            gateS[n] = 0.5f * x * (1.f + erff(x * 0.70710678118f));
        }
    }
    __syncthreads();

    // ---- logits + softmax (warps 0..3) ----
    if (w < 4) {
        const int m0 = w * 16;
        const size_t q0 = lo_row(m0 + g);      // row g
        const size_t q1 = lo_row(m0 + g + 8);  // row g+8
        float c[2][4];
#pragma unroll
        for (int nt = 0; nt < 2; nt++)
#pragma unroll
            for (int q = 0; q < 4; q++) c[nt][q] = 0.f;

#pragma unroll 4
        for (int k16 = 0; k16 < 512; k16 += 16) {
            uint32_t a[4], bb0[2], bb1[2];
            a[0] = *(const uint32_t*)&g_Q[q0 + k16 + tg * 2];
            a[1] = *(const uint32_t*)&g_Q[q1 + k16 + tg * 2];
            a[2] = *(const uint32_t*)&g_Q[q0 + k16 + tg * 2 + 8];
            a[3] = *(const uint32_t*)&g_Q[q1 + k16 + tg * 2 + 8];
            bb0[0] = *(const uint32_t*)&Ks[g * 520 + k16 + tg * 2];
            bb0[1] = *(const uint32_t*)&Ks[g * 520 + k16 + tg * 2 + 8];
            bb1[0] = *(const uint32_t*)&Ks[(8 + g) * 520 + k16 + tg * 2];
            bb1[1] = *(const uint32_t*)&Ks[(8 + g) * 520 + k16 + tg * 2 + 8];
            mma16816(c[0], a, bb0);
            mma16816(c[1], a, bb1);
        }

        // softmax per row; row g holds c[0][0],c[0][1],c[1][0],c[1][1]
        // row g+8 holds c[0][2],c[0][3],c[1][2],c[1][3]; cols nt*8+2tg(+1)
        const float scale = 0.044194173824159216f;  // 512^-0.5
#pragma unroll
        for (int half = 0; half < 2; half++) {
            const int row = m0 + g + half * 8;
            float v0 = c[0][half * 2], v1 = c[0][half * 2 + 1];
            float v2 = c[1][half * 2], v3 = c[1][half * 2 + 1];
            float m = fmaxf(fmaxf(v0, v1), fmaxf(v2, v3));
            m = fmaxf(m, __shfl_xor_sync(0xffffffffu, m, 1));
            m = fmaxf(m, __shfl_xor_sync(0xffffffffu, m, 2));
            v0 = __expf((v0 - m) * scale);
            v1 = __expf((v1 - m) * scale);
            v2 = __expf((v2 - m) * scale);
            v3 = __expf((v3 - m) * scale);
            float ssum = v0 + v1 + v2 + v3;
            ssum += __shfl_xor_sync(0xffffffffu, ssum, 1);
            ssum += __shfl_xor_sync(0xffffffffu, ssum, 2);
            const float gm = gateS[row] / ssum;
            Wgt[row * 16 + 2 * tg]     = v0 * gm;
            Wgt[row * 16 + 2 * tg + 1] = v1 * gm;
            Wgt[row * 16 + 8 + 2 * tg]     = v2 * gm;
            Wgt[row * 16 + 8 + 2 * tg + 1] = v3 * gm;
        }
    }
    __syncthreads();

    // ---- AV + residual (all warps; warp w owns rows 8w..8w+7) ----
#pragma unroll 1
    for (int rgrp = 0; rgrp < 2; rgrp++) {
        const int r0 = w * 8 + rgrp * 4;
        size_t lrow[4];
#pragma unroll
        for (int r = 0; r < 4; r++) lrow[r] = lo_row(r0 + r);

#pragma unroll 1
        for (int chunk = 0; chunk < 2; chunk++) {
            float2 acc[4][4];
#pragma unroll
            for (int r = 0; r < 4; r++)
#pragma unroll
                for (int i = 0; i < 4; i++) acc[r][i] = make_float2(0.f, 0.f);

#pragma unroll
            for (int j = 0; j < 16; j++) {
                float wj[4];
#pragma unroll
                for (int r = 0; r < 4; r++) wj[r] = Wgt[(r0 + r) * 16 + j];
#pragma unroll
                for (int i = 0; i < 4; i++) {
                    const int c2 = lane + 32 * (chunk * 4 + i);
                    const float2 vv =
                        __bfloat1622float2(*(const __nv_bfloat162*)&Vs[j * 520 + 2 * c2]);
#pragma unroll
                    for (int r = 0; r < 4; r++)
                        fma2(acc[r][i], make_float2(wj[r], wj[r]), vv);
                }
            }
#pragma unroll
            for (int r = 0; r < 4; r++) {
#pragma unroll
                for (int i = 0; i < 4; i++) {
                    const int c2 = lane + 32 * (chunk * 4 + i);
                    const float2 res = *(const float2*)&lo[lrow[r] + 2 * c2];
                    float2 o;
                    o.x = acc[r][i].x + res.x;
                    o.y = acc[r][i].y + res.y;
                    *(float2*)&out[lrow[r] + 2 * c2] = o;
                }
            }
        }
    }
}

// ---------------------------------------------------------------------------
// launch
// ---------------------------------------------------------------------------
extern "C" void kernel_launch(void* const* d_in, const int* in_sizes, int n_in,
                              void* d_out, int out_size) {
    const float* lo = (const float*)d_in[0];
    const float* hi = (const float*)d_in[1];
    const float* Wq = (const float*)d_in[2];
    const float* bq = (const float*)d_in[3];
    const float* Wk = (const float*)d_in[4];
    const float* bk = (const float*)d_in[5];
    const float* Wv = (const float*)d_in[6];
    const float* bv = (const float*)d_in[7];
    const float* Ws = (const float*)d_in[8];
    const float* bs = (const float*)d_in[9];
    float* out = (float*)d_out;

    const int B = in_sizes[0] / (3136 * 512);   // 32
    const int mQ = (B * 3136) / 128;            // 784
    const int mKV = (B * 784) / 128;            // 196

    proj_gemm_kernel<<<dim3(4, mQ), 256>>>(lo, Wq, bq, Wq, bq, 0);
    proj_gemm_kernel<<<dim3(8, mKV), 256>>>(hi, Wk, bk, Wv, bv, 1);
    attn_kernel<<<dim3(49, B), 256>>>(lo, Ws, bs, out);
}